// round 4
// baseline (speedup 1.0000x reference)
#include <cuda_runtime.h>
#include <cstdint>
#include <cstddef>

// ---------------- problem constants ----------------
#define T_TOK 4096
#define D_DIM 1024
#define F_DIM 2816
#define F2_DIM 5632
#define N_EXP 8
#define TK 8192

// ---------------- tiling ----------------
// BM=128, BN=128, BK=32, 256 threads (8 warps, 2x4), 3-stage cp.async
#define ROWF 36                    // floats per padded smem row (144 B)
#define MAT_ST (128 * ROWF)        // 4608 floats per matrix per stage
#define STAGE_F (2 * MAT_ST)       // A + B
#define SMEM_B (3 * STAGE_F * 4)   // 110592 bytes
#define GRIDX 10                   // row-block stride

// ---------------- device scratch ----------------
__device__ int   g_offsets[N_EXP + 1];
__device__ int   g_tok[TK];
__device__ int   g_pos[TK];
__device__ float g_wt[TK];
__device__ float g_h[(size_t)TK * F_DIM];   // SwiGLU intermediate (tf32-rounded)
__device__ float g_o[(size_t)TK * D_DIM];   // per-slot down output

// ---------------- helpers ----------------
__device__ __forceinline__ unsigned f2tf(float x) {
    unsigned r;
    asm("cvt.rna.tf32.f32 %0, %1;" : "=r"(r) : "f"(x));
    return r;
}
__device__ __forceinline__ unsigned f2tf_u(unsigned x) {
    unsigned r;
    asm("cvt.rna.tf32.f32 %0, %1;" : "=r"(r) : "f"(__uint_as_float(x)));
    return r;
}
__device__ __forceinline__ uint32_t cvta_s(const void* p) {
    return (uint32_t)__cvta_generic_to_shared(p);
}
__device__ __forceinline__ void cpasync16(void* smem_ptr, const void* gptr) {
    unsigned s = cvta_s(smem_ptr);
    asm volatile("cp.async.cg.shared.global [%0], [%1], 16;" ::"r"(s), "l"(gptr));
}
__device__ __forceinline__ void cp_commit() { asm volatile("cp.async.commit_group;"); }
__device__ __forceinline__ void cp_wait0() { asm volatile("cp.async.wait_group 0;"); }
__device__ __forceinline__ void cp_wait1() { asm volatile("cp.async.wait_group 1;"); }

__device__ __forceinline__ void ldsm4(uint32_t r[4], uint32_t addr) {
    asm volatile("ldmatrix.sync.aligned.m8n8.x4.shared.b16 {%0,%1,%2,%3}, [%4];"
                 : "=r"(r[0]), "=r"(r[1]), "=r"(r[2]), "=r"(r[3]) : "r"(addr));
}
__device__ __forceinline__ void mma_tf32(float c[4], const uint32_t a[4],
                                         uint32_t b0, uint32_t b1) {
    asm volatile(
        "mma.sync.aligned.m16n8k8.row.col.f32.tf32.tf32.f32 "
        "{%0,%1,%2,%3},{%4,%5,%6,%7},{%8,%9},{%0,%1,%2,%3};"
        : "+f"(c[0]), "+f"(c[1]), "+f"(c[2]), "+f"(c[3])
        : "r"(a[0]), "r"(a[1]), "r"(a[2]), "r"(a[3]), "r"(b0), "r"(b1));
}

// ---------------- routing: bucket entries by expert ----------------
__global__ void routing_kernel(const void* sel_raw, const float* __restrict__ rw) {
    __shared__ int sc[N_EXP];
    __shared__ int scur[N_EXP];
    __shared__ int smode;
    int tid = threadIdx.x;
    if (tid < N_EXP) sc[tid] = 0;
    if (tid == 0) {
        const int* s32 = (const int*)sel_raw;
        int any = 0;
        #pragma unroll
        for (int i = 0; i < 8; i++) any |= s32[2 * i + 1];
        smode = any ? 0 : 1;  // 1 = int64
    }
    __syncthreads();
    int mode = smode;
    const long long* s64 = (const long long*)sel_raw;
    const int* s32 = (const int*)sel_raw;
    for (int i = tid; i < TK; i += blockDim.x) {
        int e = mode ? (int)s64[i] : s32[i];
        atomicAdd(&sc[e], 1);
    }
    __syncthreads();
    if (tid == 0) {
        int off = 0;
        for (int e = 0; e < N_EXP; e++) { g_offsets[e] = off; scur[e] = off; off += sc[e]; }
        g_offsets[N_EXP] = off;
    }
    __syncthreads();
    for (int i = tid; i < TK; i += blockDim.x) {
        int e = mode ? (int)s64[i] : s32[i];
        int p = atomicAdd(&scur[e], 1);
        g_tok[p] = i >> 1;
        g_pos[p] = i;
        g_wt[p] = rw[i];
    }
}

// ---------------- shared mainloop ----------------
// A: 128 x 32 f32 per stage (this thread loads row tid>>1)
// B: 128 x 32 f32 per stage. Fragments cvt'd to tf32(rna) post-ldsm.
// cc[mt][nt][4]; warp grid 2x4 (wm: 64 m-rows, wn: 32 n-rows).
__device__ __forceinline__ void mma_loop(float* sm, const float* a_src,
                                         const float* b_src, int KT,
                                         float cc[4][4][4]) {
    const int tid = threadIdx.x;
    const int lane = tid & 31;
    const int warp = tid >> 5;
    const int wm = warp >> 2, wn = warp & 3;
    const int lr = tid >> 1;
    const int cb = (tid & 1) * 4;
    const int kkx = (warp & 1) << 1;  // de-phase: odd warps rotate kk order

    const uint32_t smem0 = cvta_s(sm);
    uint32_t a_off[4], b_off[2];
    {
        const int rbase = wm * 64 + (lane & 8) + (lane & 7);
        const int achunk = (lane >> 4);
        #pragma unroll
        for (int mt = 0; mt < 4; mt++)
            a_off[mt] = (uint32_t)((rbase + mt * 16) * 144 + achunk * 16);
        const int nbase = wn * 32 + ((lane >> 4) << 3) + (lane & 7);
        const int bchunk = (lane >> 3) & 1;
        #pragma unroll
        for (int n2 = 0; n2 < 2; n2++)
            b_off[n2] = (uint32_t)(MAT_ST * 4 + (nbase + n2 * 16) * 144 + bchunk * 16);
    }

    auto load_stage = [&](int kt) {
        const int s = kt % 3;
        const float* As = a_src + kt * 32;
        const float* Bs = b_src + kt * 32;
        float* dA = sm + s * STAGE_F + lr * ROWF;
        float* dB = dA + MAT_ST;
        #pragma unroll
        for (int i = 0; i < 4; i++) {
            const int c = cb + i;
            cpasync16(dA + c * 4, As + c * 4);
            cpasync16(dB + c * 4, Bs + c * 4);
        }
        cp_commit();
    };

    load_stage(0);
    load_stage(1);

    for (int kt = 0; kt < KT; kt++) {
        if (kt + 1 < KT) cp_wait1(); else cp_wait0();
        __syncthreads();
        if (kt + 2 < KT) load_stage(kt + 2);

        const uint32_t base = smem0 + (uint32_t)((kt % 3) * STAGE_F * 4);
        #pragma unroll
        for (int kq = 0; kq < 4; kq++) {
            const int kk = kq ^ kkx;
            uint32_t a[4][4], b[2][4];
            #pragma unroll
            for (int mt = 0; mt < 4; mt++) {
                ldsm4(a[mt], base + a_off[mt] + kk * 32);
                #pragma unroll
                for (int j = 0; j < 4; j++) a[mt][j] = f2tf_u(a[mt][j]);
            }
            #pragma unroll
            for (int n2 = 0; n2 < 2; n2++) {
                ldsm4(b[n2], base + b_off[n2] + kk * 32);
                #pragma unroll
                for (int j = 0; j < 4; j++) b[n2][j] = f2tf_u(b[n2][j]);
            }
            #pragma unroll
            for (int mt = 0; mt < 4; mt++)
                #pragma unroll
                for (int nt = 0; nt < 4; nt++)
                    mma_tf32(cc[mt][nt], a[mt], b[nt >> 1][(nt & 1) * 2],
                             b[nt >> 1][(nt & 1) * 2 + 1]);
        }
    }
    __syncthreads();  // smem safe for next row-block
}

// ---------------- GEMM1: X @ Wgu^T (+SwiGLU) -> g_h ----------------
// B rows interleave gate/up by parity: thread's (c0,c1) = (gate,up).
__global__ void __launch_bounds__(256, 2)
gemm1_k(const float* __restrict__ X, const float* __restrict__ Wgu) {
    const int e = blockIdx.z;
    const int base = g_offsets[e];
    const int n_e = g_offsets[e + 1] - base;
    const int col0 = blockIdx.y * 64;  // h columns per tile

    extern __shared__ float sm[];
    const int tid = threadIdx.x;
    const int lane = tid & 31, warp = tid >> 5;
    const int wm = warp >> 2, wn = warp & 3;
    const int lr = tid >> 1;

    const int wrow = col0 + (lr >> 1) + ((lr & 1) ? F_DIM : 0);
    const float* b_src = Wgu + ((size_t)e * F2_DIM + wrow) * D_DIM;

    for (int rb = blockIdx.x; rb * 128 < n_e; rb += GRIDX) {
        const int row0 = rb * 128;
        int ge = base + row0 + lr;
        if (ge > TK - 1) ge = TK - 1;
        const float* a_src = X + (size_t)g_tok[ge] * D_DIM;

        float cc[4][4][4];
        #pragma unroll
        for (int a = 0; a < 4; a++)
            #pragma unroll
            for (int b = 0; b < 4; b++)
                #pragma unroll
                for (int c = 0; c < 4; c++) cc[a][b][c] = 0.f;

        mma_loop(sm, a_src, b_src, D_DIM / 32, cc);

        const int rbase = wm * 64 + (lane >> 2);
        const int jbase = col0 + wn * 16 + (lane & 3);
        #pragma unroll
        for (int mt = 0; mt < 4; mt++) {
            const int r0 = rbase + mt * 16;
            #pragma unroll
            for (int nt = 0; nt < 4; nt++) {
                const int j = jbase + nt * 4;
                if (row0 + r0 < n_e) {
                    float g = cc[mt][nt][0], u = cc[mt][nt][1];
                    float h = g * u / (1.f + __expf(-g));
                    g_h[(size_t)(base + row0 + r0) * F_DIM + j] = __uint_as_float(f2tf(h));
                }
                if (row0 + r0 + 8 < n_e) {
                    float g = cc[mt][nt][2], u = cc[mt][nt][3];
                    float h = g * u / (1.f + __expf(-g));
                    g_h[(size_t)(base + row0 + r0 + 8) * F_DIM + j] = __uint_as_float(f2tf(h));
                }
            }
        }
    }
}

// ---------------- GEMM2: g_h @ Wd^T, scale, per-slot store ----------------
__global__ void __launch_bounds__(256, 2)
gemm2_k(const float* __restrict__ Wd) {
    const int e = blockIdx.z;
    const int base = g_offsets[e];
    const int n_e = g_offsets[e + 1] - base;
    const int col0 = blockIdx.y * 128;  // over D

    extern __shared__ float sm[];
    const int tid = threadIdx.x;
    const int lane = tid & 31, warp = tid >> 5;
    const int wm = warp >> 2, wn = warp & 3;
    const int lr = tid >> 1;

    const float* b_src = Wd + ((size_t)e * D_DIM + col0 + lr) * F_DIM;

    for (int rb = blockIdx.x; rb * 128 < n_e; rb += GRIDX) {
        const int row0 = rb * 128;
        int ge = base + row0 + lr;
        if (ge > TK - 1) ge = TK - 1;
        const float* a_src = g_h + (size_t)ge * F_DIM;

        float cc[4][4][4];
        #pragma unroll
        for (int a = 0; a < 4; a++)
            #pragma unroll
            for (int b = 0; b < 4; b++)
                #pragma unroll
                for (int c = 0; c < 4; c++) cc[a][b][c] = 0.f;

        mma_loop(sm, a_src, b_src, F_DIM / 32, cc);

        const int rbase = wm * 64 + (lane >> 2);
        const int colb = col0 + wn * 32 + 2 * (lane & 3);
        #pragma unroll
        for (int mt = 0; mt < 4; mt++) {
            const int r0 = rbase + mt * 16;
            #pragma unroll
            for (int half = 0; half < 2; half++) {
                const int r = r0 + half * 8;
                if (row0 + r < n_e) {
                    const int gi = base + row0 + r;
                    const int pos = g_pos[gi];
                    const float wt = g_wt[gi];
                    float* orow = g_o + (size_t)pos * D_DIM;
                    #pragma unroll
                    for (int nt = 0; nt < 4; nt++) {
                        const int col = colb + nt * 8;
                        float2 v;
                        v.x = cc[mt][nt][half * 2 + 0] * wt;
                        v.y = cc[mt][nt][half * 2 + 1] * wt;
                        *(float2*)(orow + col) = v;
                    }
                }
            }
        }
    }
}

// ---------------- combine the 2 slots per token ----------------
__global__ void combine_kernel(float4* __restrict__ out) {
    const int RD = D_DIM / 4;
    int i = blockIdx.x * blockDim.x + threadIdx.x;
    if (i < T_TOK * RD) {
        int t = i / RD, r = i % RD;
        const float4* go = (const float4*)g_o;
        float4 a = go[(size_t)(2 * t) * RD + r];
        float4 b = go[(size_t)(2 * t + 1) * RD + r];
        out[i] = make_float4(a.x + b.x, a.y + b.y, a.z + b.z, a.w + b.w);
    }
}

// ---------------- launch ----------------
extern "C" void kernel_launch(void* const* d_in, const int* in_sizes, int n_in,
                              void* d_out, int out_size) {
    const float* X   = (const float*)d_in[0];
    const float* rw  = (const float*)d_in[1];
    const float* Wgu = (const float*)d_in[2];
    const float* Wd  = (const float*)d_in[3];
    const void*  sel = d_in[4];
    float* out = (float*)d_out;

    cudaFuncSetAttribute(gemm1_k, cudaFuncAttributeMaxDynamicSharedMemorySize, SMEM_B);
    cudaFuncSetAttribute(gemm2_k, cudaFuncAttributeMaxDynamicSharedMemorySize, SMEM_B);

    routing_kernel<<<1, 1024>>>(sel, rw);
    gemm1_k<<<dim3(GRIDX, F_DIM / 64, N_EXP), 256, SMEM_B>>>(X, Wgu);
    gemm2_k<<<dim3(GRIDX, D_DIM / 128, N_EXP), 256, SMEM_B>>>(Wd);
    combine_kernel<<<(T_TOK * D_DIM / 4 + 255) / 256, 256>>>((float4*)out);
}

// round 5
// speedup vs baseline: 1.0570x; 1.0570x over previous
#include <cuda_runtime.h>
#include <cstdint>
#include <cstddef>

// ---------------- problem constants ----------------
#define T_TOK 4096
#define D_DIM 1024
#define F_DIM 2816
#define F2_DIM 5632
#define N_EXP 8
#define TK 8192

// ---------------- tiling ----------------
// BM=128, BN=128, BK=32, 256 threads (8 warps, 2x4), 5-stage cp.async,
// XOR-swizzled 128B smem rows (no padding), 1 CTA/SM.
#define N_ST 5
#define MAT_B 16384                 // 128 rows * 128 B
#define STAGE_BYTES (2 * MAT_B)     // A + B = 32 KB
#define SMEM_BYTES (N_ST * STAGE_BYTES)  // 160 KB
#define GRIDX 10

// ---------------- device scratch ----------------
__device__ int   g_offsets[N_EXP + 1];
__device__ int   g_tok[TK];
__device__ int   g_pos[TK];
__device__ float g_wt[TK];
__device__ float g_xr[(size_t)T_TOK * D_DIM];  // rna-rounded X
__device__ float g_h[(size_t)TK * F_DIM];      // SwiGLU intermediate (rounded)
__device__ float g_o[(size_t)TK * D_DIM];      // per-slot down output

// ---------------- helpers ----------------
__device__ __forceinline__ unsigned f2tf(float x) {
    unsigned r;
    asm("cvt.rna.tf32.f32 %0, %1;" : "=r"(r) : "f"(x));
    return r;
}
__device__ __forceinline__ unsigned f2tf_u(unsigned x) {
    unsigned r;
    asm("cvt.rna.tf32.f32 %0, %1;" : "=r"(r) : "f"(__uint_as_float(x)));
    return r;
}
__device__ __forceinline__ uint32_t cvta_s(const void* p) {
    return (uint32_t)__cvta_generic_to_shared(p);
}
__device__ __forceinline__ void cpasync16(uint32_t smem_addr, const void* gptr) {
    asm volatile("cp.async.cg.shared.global [%0], [%1], 16;" ::"r"(smem_addr), "l"(gptr));
}
__device__ __forceinline__ void cp_commit() { asm volatile("cp.async.commit_group;"); }
__device__ __forceinline__ void cp_waitg(int left) {
    // immediate-operand forms
    if (left == 0) asm volatile("cp.async.wait_group 0;");
    else if (left == 1) asm volatile("cp.async.wait_group 1;");
    else if (left == 2) asm volatile("cp.async.wait_group 2;");
    else asm volatile("cp.async.wait_group 3;");
}

__device__ __forceinline__ void ldsm4(uint32_t r[4], uint32_t addr) {
    asm volatile("ldmatrix.sync.aligned.m8n8.x4.shared.b16 {%0,%1,%2,%3}, [%4];"
                 : "=r"(r[0]), "=r"(r[1]), "=r"(r[2]), "=r"(r[3]) : "r"(addr));
}
__device__ __forceinline__ void mma_tf32(float c[4], const uint32_t a[4],
                                         uint32_t b0, uint32_t b1) {
    asm volatile(
        "mma.sync.aligned.m16n8k8.row.col.f32.tf32.tf32.f32 "
        "{%0,%1,%2,%3},{%4,%5,%6,%7},{%8,%9},{%0,%1,%2,%3};"
        : "+f"(c[0]), "+f"(c[1]), "+f"(c[2]), "+f"(c[3])
        : "r"(a[0]), "r"(a[1]), "r"(a[2]), "r"(a[3]), "r"(b0), "r"(b1));
}

// ---------------- pre-round X to tf32(rna) ----------------
__global__ void round_x(const float4* __restrict__ x) {
    int i = blockIdx.x * blockDim.x + threadIdx.x;
    if (i < T_TOK * D_DIM / 4) {
        float4 v = x[i];
        v.x = __uint_as_float(f2tf(v.x));
        v.y = __uint_as_float(f2tf(v.y));
        v.z = __uint_as_float(f2tf(v.z));
        v.w = __uint_as_float(f2tf(v.w));
        ((float4*)g_xr)[i] = v;
    }
}

// ---------------- routing ----------------
__global__ void routing_kernel(const void* sel_raw, const float* __restrict__ rw) {
    __shared__ int sc[N_EXP];
    __shared__ int scur[N_EXP];
    __shared__ int smode;
    int tid = threadIdx.x;
    if (tid < N_EXP) sc[tid] = 0;
    if (tid == 0) {
        const int* s32 = (const int*)sel_raw;
        int any = 0;
        #pragma unroll
        for (int i = 0; i < 8; i++) any |= s32[2 * i + 1];
        smode = any ? 0 : 1;  // 1 = int64
    }
    __syncthreads();
    int mode = smode;
    const long long* s64 = (const long long*)sel_raw;
    const int* s32 = (const int*)sel_raw;
    for (int i = tid; i < TK; i += blockDim.x) {
        int e = mode ? (int)s64[i] : s32[i];
        atomicAdd(&sc[e], 1);
    }
    __syncthreads();
    if (tid == 0) {
        int off = 0;
        for (int e = 0; e < N_EXP; e++) { g_offsets[e] = off; scur[e] = off; off += sc[e]; }
        g_offsets[N_EXP] = off;
    }
    __syncthreads();
    for (int i = tid; i < TK; i += blockDim.x) {
        int e = mode ? (int)s64[i] : s32[i];
        int p = atomicAdd(&scur[e], 1);
        g_tok[p] = i >> 1;
        g_pos[p] = i;
        g_wt[p] = rw[i];
    }
}

// ---------------- shared mainloop ----------------
// A rows pre-rounded (g_xr / g_h); B (weights) cvt'd post-ldsm.
// smem row = 128 B, chunk c (16B) stored at ((c ^ (row&7)) * 16).
__device__ __forceinline__ void mma_loop(uint32_t smem0, const float* a_src,
                                         const float* b_src, int KT,
                                         float cc[4][4][4]) {
    const int tid = threadIdx.x;
    const int lane = tid & 31;
    const int warp = tid >> 5;
    const int wm = warp >> 2, wn = warp & 3;
    const int lr = tid >> 1;
    const int cb = (tid & 1) * 4;

    // ldsm bases (per-stage-relative) + per-lane xor components
    uint32_t a_base[4], b_base[2];
    {
        const int arow = wm * 64 + (lane & 8) + (lane & 7);
        #pragma unroll
        for (int mt = 0; mt < 4; mt++)
            a_base[mt] = (uint32_t)((arow + mt * 16) * 128);
        const int brow = wn * 32 + ((lane >> 4) << 3) + (lane & 7);
        #pragma unroll
        for (int n2 = 0; n2 < 2; n2++)
            b_base[n2] = (uint32_t)(MAT_B + (brow + n2 * 16) * 128);
    }
    const uint32_t axr = (uint32_t)((lane >> 4) ^ (lane & 7));        // achunk ^ row&7
    const uint32_t bxr = (uint32_t)(((lane >> 3) & 1) ^ (lane & 7));  // bchunk ^ row&7

    // cp.async dst offsets (per-stage-relative), swizzled
    uint32_t stA[4], stB[4];
    #pragma unroll
    for (int i = 0; i < 4; i++) {
        const int c = cb + i;
        const uint32_t sw = (uint32_t)(((c ^ (lr & 7)) << 4));
        stA[i] = (uint32_t)(lr * 128) + sw;
        stB[i] = (uint32_t)(MAT_B + lr * 128) + sw;
    }

    auto load_stage = [&](int kt) {
        const uint32_t sb = smem0 + (uint32_t)((kt % N_ST) * STAGE_BYTES);
        const float* As = a_src + kt * 32;
        const float* Bs = b_src + kt * 32;
        #pragma unroll
        for (int i = 0; i < 4; i++) {
            const int c = cb + i;
            cpasync16(sb + stA[i], As + c * 4);
            cpasync16(sb + stB[i], Bs + c * 4);
        }
        cp_commit();
    };

    #pragma unroll
    for (int s = 0; s < 4; s++) load_stage(s);

    for (int kt = 0; kt < KT; kt++) {
        const int rem = KT - 1 - kt;
        cp_waitg(rem < 3 ? rem : 3);
        __syncthreads();
        if (kt + 4 < KT) load_stage(kt + 4);

        const uint32_t base = smem0 + (uint32_t)((kt % N_ST) * STAGE_BYTES);
        #pragma unroll
        for (int kk = 0; kk < 4; kk++) {
            const uint32_t kk2 = (uint32_t)(kk << 1);
            const uint32_t swA = ((kk2 ^ axr) << 4);
            const uint32_t swB = ((kk2 ^ bxr) << 4);
            uint32_t a[4][4], b[2][4];
            #pragma unroll
            for (int mt = 0; mt < 4; mt++)
                ldsm4(a[mt], base + a_base[mt] + swA);
            #pragma unroll
            for (int n2 = 0; n2 < 2; n2++) {
                ldsm4(b[n2], base + b_base[n2] + swB);
                #pragma unroll
                for (int j = 0; j < 4; j++) b[n2][j] = f2tf_u(b[n2][j]);
            }
            #pragma unroll
            for (int mt = 0; mt < 4; mt++)
                #pragma unroll
                for (int nt = 0; nt < 4; nt++)
                    mma_tf32(cc[mt][nt], a[mt], b[nt >> 1][(nt & 1) * 2],
                             b[nt >> 1][(nt & 1) * 2 + 1]);
        }
    }
    __syncthreads();  // smem safe for next row-block
}

// ---------------- GEMM1: X @ Wgu^T (+SwiGLU) -> g_h ----------------
__global__ void __launch_bounds__(256, 1)
gemm1_k(const float* __restrict__ Wgu) {
    const int e = blockIdx.z;
    const int base = g_offsets[e];
    const int n_e = g_offsets[e + 1] - base;
    const int col0 = blockIdx.y * 64;  // h columns per tile

    extern __shared__ __align__(128) char smraw[];
    const uint32_t smem0 = cvta_s(smraw);
    const int tid = threadIdx.x;
    const int lane = tid & 31, warp = tid >> 5;
    const int wm = warp >> 2, wn = warp & 3;
    const int lr = tid >> 1;

    const int wrow = col0 + (lr >> 1) + ((lr & 1) ? F_DIM : 0);
    const float* b_src = Wgu + ((size_t)e * F2_DIM + wrow) * D_DIM;

    for (int rb = blockIdx.x; rb * 128 < n_e; rb += GRIDX) {
        const int row0 = rb * 128;
        int ge = base + row0 + lr;
        if (ge > TK - 1) ge = TK - 1;
        const float* a_src = g_xr + (size_t)g_tok[ge] * D_DIM;

        float cc[4][4][4];
        #pragma unroll
        for (int a = 0; a < 4; a++)
            #pragma unroll
            for (int b = 0; b < 4; b++)
                #pragma unroll
                for (int c = 0; c < 4; c++) cc[a][b][c] = 0.f;

        mma_loop(smem0, a_src, b_src, D_DIM / 32, cc);

        const int rbase = wm * 64 + (lane >> 2);
        const int jbase = col0 + wn * 16 + (lane & 3);
        #pragma unroll
        for (int mt = 0; mt < 4; mt++) {
            const int r0 = rbase + mt * 16;
            #pragma unroll
            for (int nt = 0; nt < 4; nt++) {
                const int j = jbase + nt * 4;
                if (row0 + r0 < n_e) {
                    float g = cc[mt][nt][0], u = cc[mt][nt][1];
                    float h = g * u / (1.f + __expf(-g));
                    g_h[(size_t)(base + row0 + r0) * F_DIM + j] = __uint_as_float(f2tf(h));
                }
                if (row0 + r0 + 8 < n_e) {
                    float g = cc[mt][nt][2], u = cc[mt][nt][3];
                    float h = g * u / (1.f + __expf(-g));
                    g_h[(size_t)(base + row0 + r0 + 8) * F_DIM + j] = __uint_as_float(f2tf(h));
                }
            }
        }
    }
}

// ---------------- GEMM2: g_h @ Wd^T, scale, per-slot store ----------------
__global__ void __launch_bounds__(256, 1)
gemm2_k(const float* __restrict__ Wd) {
    const int e = blockIdx.z;
    const int base = g_offsets[e];
    const int n_e = g_offsets[e + 1] - base;
    const int col0 = blockIdx.y * 128;  // over D

    extern __shared__ __align__(128) char smraw[];
    const uint32_t smem0 = cvta_s(smraw);
    const int tid = threadIdx.x;
    const int lane = tid & 31, warp = tid >> 5;
    const int wm = warp >> 2, wn = warp & 3;
    const int lr = tid >> 1;

    const float* b_src = Wd + ((size_t)e * D_DIM + col0 + lr) * F_DIM;

    for (int rb = blockIdx.x; rb * 128 < n_e; rb += GRIDX) {
        const int row0 = rb * 128;
        int ge = base + row0 + lr;
        if (ge > TK - 1) ge = TK - 1;
        const float* a_src = g_h + (size_t)ge * F_DIM;

        float cc[4][4][4];
        #pragma unroll
        for (int a = 0; a < 4; a++)
            #pragma unroll
            for (int b = 0; b < 4; b++)
                #pragma unroll
                for (int c = 0; c < 4; c++) cc[a][b][c] = 0.f;

        mma_loop(smem0, a_src, b_src, F_DIM / 32, cc);

        const int rbase = wm * 64 + (lane >> 2);
        const int colb = col0 + wn * 32 + 2 * (lane & 3);
        #pragma unroll
        for (int mt = 0; mt < 4; mt++) {
            const int r0 = rbase + mt * 16;
            #pragma unroll
            for (int half = 0; half < 2; half++) {
                const int r = r0 + half * 8;
                if (row0 + r < n_e) {
                    const int gi = base + row0 + r;
                    const int pos = g_pos[gi];
                    const float wt = g_wt[gi];
                    float* orow = g_o + (size_t)pos * D_DIM;
                    #pragma unroll
                    for (int nt = 0; nt < 4; nt++) {
                        const int col = colb + nt * 8;
                        float2 v;
                        v.x = cc[mt][nt][half * 2 + 0] * wt;
                        v.y = cc[mt][nt][half * 2 + 1] * wt;
                        *(float2*)(orow + col) = v;
                    }
                }
            }
        }
    }
}

// ---------------- combine the 2 slots per token ----------------
__global__ void combine_kernel(float4* __restrict__ out) {
    const int RD = D_DIM / 4;
    int i = blockIdx.x * blockDim.x + threadIdx.x;
    if (i < T_TOK * RD) {
        int t = i / RD, r = i % RD;
        const float4* go = (const float4*)g_o;
        float4 a = go[(size_t)(2 * t) * RD + r];
        float4 b = go[(size_t)(2 * t + 1) * RD + r];
        out[i] = make_float4(a.x + b.x, a.y + b.y, a.z + b.z, a.w + b.w);
    }
}

// ---------------- launch ----------------
extern "C" void kernel_launch(void* const* d_in, const int* in_sizes, int n_in,
                              void* d_out, int out_size) {
    const float* X   = (const float*)d_in[0];
    const float* rw  = (const float*)d_in[1];
    const float* Wgu = (const float*)d_in[2];
    const float* Wd  = (const float*)d_in[3];
    const void*  sel = d_in[4];
    float* out = (float*)d_out;

    cudaFuncSetAttribute(gemm1_k, cudaFuncAttributeMaxDynamicSharedMemorySize, SMEM_BYTES);
    cudaFuncSetAttribute(gemm2_k, cudaFuncAttributeMaxDynamicSharedMemorySize, SMEM_BYTES);

    round_x<<<(T_TOK * D_DIM / 4 + 255) / 256, 256>>>((const float4*)X);
    routing_kernel<<<1, 1024>>>(sel, rw);
    gemm1_k<<<dim3(GRIDX, F_DIM / 64, N_EXP), 256, SMEM_BYTES>>>(Wgu);
    gemm2_k<<<dim3(GRIDX, D_DIM / 128, N_EXP), 256, SMEM_BYTES>>>(Wd);
    combine_kernel<<<(T_TOK * D_DIM / 4 + 255) / 256, 256>>>((float4*)out);
}